// round 14
// baseline (speedup 1.0000x reference)
#include <cuda_runtime.h>
#include <cstdint>
#include <math.h>

#define DM   1024
#define NEXP 32
#define FE   128
#define TT   4
#define BATCH 4
#define SEQ  4096
#define NTOK (BATCH*SEQ)   // 16384
#define NGRP (SEQ/TT)      // 1024

typedef unsigned long long ull;

// scratch (device globals; no allocation)
__device__ float g_logitsT[BATCH*TT*NEXP*NGRP];   // 2MB [(b*4+t)*32+e][g]
__device__ int   g_selg[BATCH*TT*NEXP];
__device__ float g_selp[BATCH*TT*NEXP];

__device__ __forceinline__ ull pack2(float a, float b) {
    ull r; asm("mov.b64 %0,{%1,%2};" : "=l"(r) : "f"(a), "f"(b)); return r;
}
__device__ __forceinline__ void unpack2(ull v, float& a, float& b) {
    asm("mov.b64 {%0,%1},%2;" : "=f"(a), "=f"(b) : "l"(v));
}
__device__ __forceinline__ void ffma2(ull& d, ull a, ull b) {
    asm("fma.rn.f32x2 %0,%1,%2,%0;" : "+l"(d) : "l"(a), "l"(b));
}

// ---------------------------------------------------------------------------
// K1: zero output + logits GEMM. 128 blocks x 1024 threads (1 block/SM,
// 32 warps = 8 warps/SMSP). warp = (tq, eq, ks): tq = token half (64 tok),
// eq = expert octet, ks = k-slice (8 k of each 32-k chunk).
// Thread tile: 2 tok x 8 exp (acc 8 ull -> ~55 regs, fits 64-reg cap).
// x staged transposed [k][tok] pad-129 (conflict-free STS/LDS).
// Full controller (128KB) in smem.
// ---------------------------------------------------------------------------
#define XKROW 129
#define XKBUF (32*XKROW)
#define SMEM1 (131072 + 2*XKBUF*4)              // 164096

__global__ void __launch_bounds__(1024, 1)
k_logits(const float* __restrict__ x, const float* __restrict__ ctrl,
         float* __restrict__ out)
{
    extern __shared__ char smraw[];
    ull*   ctrl_s = reinterpret_cast<ull*>(smraw);              // [1024k][16 ull]
    float* xk0    = reinterpret_cast<float*>(smraw + 131072);   // [32][129]
    float* xk1    = xk0 + XKBUF;

    const int tid = threadIdx.x;
    const int tg  = tid & 31;
    const int w   = tid >> 5;        // 0..31
    const int tq  = w >> 4;          // token half (0..1)
    const int eq  = (w >> 2) & 3;    // expert octet
    const int ks  = w & 3;           // k slice (8 k of 32-k chunk)
    const int tb  = blockIdx.x;
    const float* xblk = x + (size_t)tb * 128 * DM;

    // fire-and-forget zero of this block's output slab
    {
        float4 z = make_float4(0.f, 0.f, 0.f, 0.f);
        float4* op = reinterpret_cast<float4*>(out) + (size_t)tb * 32768;
        #pragma unroll
        for (int i = 0; i < 32; i++) op[tid + i*1024] = z;
    }

    // staging geometry: thread handles ONE float4: tok = tid>>3, kq = tid&7
    const int s_tok = tid >> 3;          // 0..127
    const int s_kq  = tid & 7;
    const float* sbase = xblk + (size_t)s_tok*DM + s_kq*4;

    float4 r0 = *reinterpret_cast<const float4*>(sbase);

    // load full controller into smem
    {
        const float4* cg4 = reinterpret_cast<const float4*>(ctrl);
        float4* cs4 = reinterpret_cast<float4*>(ctrl_s);
        #pragma unroll
        for (int i = 0; i < 8; i++) cs4[tid + i*1024] = cg4[tid + i*1024];
    }
    {
        const float* p0 = reinterpret_cast<const float*>(&r0);
        #pragma unroll
        for (int j = 0; j < 4; j++)
            xk0[(s_kq*4 + j)*XKROW + s_tok] = p0[j];
    }
    __syncthreads();

    ull acc[2][4];
    #pragma unroll
    for (int i = 0; i < 2; i++)
        #pragma unroll
        for (int p = 0; p < 4; p++) acc[i][p] = 0ull;

    for (int c = 0; c < 32; c++) {
        // issue next chunk's LDG first
        if (c < 31)
            r0 = *reinterpret_cast<const float4*>(sbase + (c+1)*32);

        // compute chunk c
        const float* xb = (c & 1) ? xk1 : xk0;
        #pragma unroll
        for (int u = 0; u < 8; u++) {
            const ulonglong2* cb = reinterpret_cast<const ulonglong2*>(
                ctrl_s + (size_t)(c*32 + ks*8 + u)*16 + eq*4);
            ulonglong2 q0 = cb[0], q1 = cb[1];
            ull cu0 = q0.x, cu1 = q0.y, cu2 = q1.x, cu3 = q1.y;
            const float* xrow = xb + (ks*8 + u)*XKROW + tq*64 + tg;
            float xf0 = xrow[0];
            float xf1 = xrow[32];
            ull x20 = pack2(xf0, xf0);
            ull x21 = pack2(xf1, xf1);
            ffma2(acc[0][0], x20, cu0);
            ffma2(acc[0][1], x20, cu1);
            ffma2(acc[0][2], x20, cu2);
            ffma2(acc[0][3], x20, cu3);
            ffma2(acc[1][0], x21, cu0);
            ffma2(acc[1][1], x21, cu1);
            ffma2(acc[1][2], x21, cu2);
            ffma2(acc[1][3], x21, cu3);
        }

        // stage chunk c+1
        if (c < 31) {
            float* bw = ((c+1) & 1) ? xk1 : xk0;
            const float* p0 = reinterpret_cast<const float*>(&r0);
            #pragma unroll
            for (int j = 0; j < 4; j++)
                bw[(s_kq*4 + j)*XKROW + s_tok] = p0[j];
        }
        __syncthreads();
    }

    // reduce over 4 k-slices via smem (reuse ctrl_s region):
    // red[(ks*128 + tok)*16 + eq*4 + p], 8192 ull = 64KB
    ull* red = ctrl_s;
    #pragma unroll
    for (int i = 0; i < 2; i++) {
        int tok = tq*64 + tg + 32*i;
        #pragma unroll
        for (int p = 0; p < 4; p++)
            red[((size_t)ks*128 + tok)*16 + eq*4 + p] = acc[i][p];
    }
    __syncthreads();

    #pragma unroll
    for (int j = 0; j < 2; j++) {
        int s = tid*2 + j;               // item = (tok, expert-pair), 0..2047
        int tok = s >> 4, pr = s & 15;
        float lo = 0.f, hi = 0.f;
        #pragma unroll
        for (int k2 = 0; k2 < 4; k2++) {
            float a, b;
            unpack2(red[((size_t)k2*128 + tok)*16 + pr], a, b);
            lo += a; hi += b;
        }
        int gt = tb*128 + tok;
        int b  = gt >> 12;
        int sg = gt & 4095;
        int g  = sg >> 2, t = sg & 3;
        float tbk = (float)t * (1e-6f / 3.0f);   // linspace(0,1e-6,4)[t]
        int row = (b*4 + t)*32 + 2*pr;
        g_logitsT[(size_t)row*1024 + g]     = lo + tbk;
        g_logitsT[(size_t)(row+1)*1024 + g] = hi + tbk;
    }
}

// ---------------------------------------------------------------------------
// K_sel: one block per (b,t,e) row: argmax + softmax denominator over 1024 g.
// ---------------------------------------------------------------------------
__global__ void __launch_bounds__(256, 8)
k_sel()
{
    __shared__ float rm[8];
    __shared__ int   rmi[8];
    __shared__ float rs[8];
    __shared__ float mfin;

    const int tid  = threadIdx.x;
    const int lane = tid & 31;
    const int wp   = tid >> 5;
    const float* L = g_logitsT + ((size_t)blockIdx.x << 10);

    float m = -3.4e38f; int mi = 0;
    #pragma unroll
    for (int j = 0; j < 4; j++) {
        int i = tid + j*256;
        float v = L[i];
        if (v > m) { m = v; mi = i; }
    }
    #pragma unroll
    for (int o = 16; o; o >>= 1) {
        float om = __shfl_down_sync(0xffffffffu, m, o);
        int   oi = __shfl_down_sync(0xffffffffu, mi, o);
        if (om > m || (om == m && oi < mi)) { m = om; mi = oi; }
    }
    if (lane == 0) { rm[wp] = m; rmi[wp] = mi; }
    __syncthreads();
    if (tid == 0) {
        #pragma unroll
        for (int w = 1; w < 8; w++) {
            if (rm[w] > m || (rm[w] == m && rmi[w] < mi)) { m = rm[w]; mi = rmi[w]; }
        }
        g_selg[blockIdx.x] = mi;
        mfin = m;
    }
    __syncthreads();
    m = mfin;

    float s = 0.f;
    #pragma unroll
    for (int j = 0; j < 4; j++) s += expf(L[tid + j*256] - m);
    #pragma unroll
    for (int o = 16; o; o >>= 1) s += __shfl_down_sync(0xffffffffu, s, o);
    if (lane == 0) rs[wp] = s;
    __syncthreads();
    if (tid == 0) {
        float tot = 0.f;
        #pragma unroll
        for (int w = 0; w < 8; w++) tot += rs[w];
        g_selp[blockIdx.x] = 1.0f / tot;
    }
}

// ---------------------------------------------------------------------------
// K2: up-proj + down-proj + scatter-add, split over 4 f-slices (R7 config).
// grid 512 = (b, e, fs) x 256 threads.
// ---------------------------------------------------------------------------
__global__ void __launch_bounds__(256, 4)
k_expert(const float* __restrict__ x, const float* __restrict__ f1,
         const float* __restrict__ bias, const float* __restrict__ f2,
         float* __restrict__ out)
{
    __shared__ float xs[4][DM];          // 16KB
    __shared__ float part[8][4][32];     // 4KB
    __shared__ float avs[4][32];
    __shared__ float Wsm[4][32];
    __shared__ int   sg[4];
    __shared__ float sp[4];

    const int tid  = threadIdx.x;
    const int lane = tid & 31;
    const int b  = blockIdx.x >> 7;
    const int e  = (blockIdx.x >> 2) & 31;
    const int fs = blockIdx.x & 3;

    if (tid < 4) {
        sg[tid] = g_selg[(b*4 + tid)*32 + e];
        sp[tid] = g_selp[(b*4 + tid)*32 + e];
    }
    __syncthreads();

    // --- load the 4 selected token rows into smem ---
    {
        const int ts = tid >> 6;
        const int gt = tid & 63;
        const float* xr = x + ((size_t)b*SEQ + sg[ts]*4 + ts) * DM;
        float4* dst = reinterpret_cast<float4*>(xs[ts]);
        const float4* src = reinterpret_cast<const float4*>(xr);
        #pragma unroll
        for (int i = 0; i < 4; i++) dst[gt + i*64] = src[gt + i*64];
    }
    __syncthreads();

    // --- up-projection for this block's 32 f's: warp w owns 128 d ---
    {
        const int w = tid >> 5;
        float a0 = 0.f, a1 = 0.f, a2 = 0.f, a3 = 0.f;
        const float* f1p = f1 + (size_t)(w*128)*(NEXP*FE) + e*FE + fs*32 + lane;
        const float* x0 = xs[0] + w*128;
        const float* x1 = xs[1] + w*128;
        const float* x2 = xs[2] + w*128;
        const float* x3 = xs[3] + w*128;
        #pragma unroll 16
        for (int d = 0; d < 128; d++) {
            float wv = f1p[(size_t)d * (NEXP*FE)];
            a0 += x0[d]*wv; a1 += x1[d]*wv; a2 += x2[d]*wv; a3 += x3[d]*wv;
        }
        part[w][0][lane] = a0; part[w][1][lane] = a1;
        part[w][2][lane] = a2; part[w][3][lane] = a3;
    }
    __syncthreads();

    if (tid < 128) {
        const int t = tid >> 5, f = tid & 31;
        float s = 0.f;
        #pragma unroll
        for (int w = 0; w < 8; w++) s += part[w][t][f];
        avs[t][f] = s;
    }
    __syncthreads();

    if (tid < 32) {
        const int f = tid;
        float av[4] = {avs[0][f], avs[1][f], avs[2][f], avs[3][f]};
        int   gg[4] = {sg[0], sg[1], sg[2], sg[3]};
        float pp[4] = {sp[0], sp[1], sp[2], sp[3]};
        float bi = bias[e*FE + fs*32 + f];
        #pragma unroll
        for (int t = 0; t < 4; t++) {
            float sum = bi;
            #pragma unroll
            for (int t2 = 0; t2 < 4; t2++)
                if (gg[t2] == gg[t]) sum += pp[t2] * av[t2];
            Wsm[t][f] = pp[t] * fmaxf(sum, 0.f);
        }
    }
    __syncthreads();

    // --- down-projection: thread owns 4 d' columns, 32 f rows ---
    {
        float o0[4] = {0,0,0,0}, o1[4] = {0,0,0,0};
        float o2[4] = {0,0,0,0}, o3[4] = {0,0,0,0};
        const float* f2p = f2 + (size_t)e*FE*DM + (size_t)(fs*32)*DM + tid*4;
        #pragma unroll 4
        for (int f = 0; f < 32; f++) {
            float4 v = *reinterpret_cast<const float4*>(f2p + (size_t)f*DM);
            float w0 = Wsm[0][f], w1 = Wsm[1][f], w2 = Wsm[2][f], w3 = Wsm[3][f];
            o0[0] += w0*v.x; o0[1] += w0*v.y; o0[2] += w0*v.z; o0[3] += w0*v.w;
            o1[0] += w1*v.x; o1[1] += w1*v.y; o1[2] += w1*v.z; o1[3] += w1*v.w;
            o2[0] += w2*v.x; o2[1] += w2*v.y; o2[2] += w2*v.z; o2[3] += w2*v.w;
            o3[0] += w3*v.x; o3[1] += w3*v.y; o3[2] += w3*v.z; o3[3] += w3*v.w;
        }
        float* ob = out + (size_t)b*SEQ*DM + tid*4;
        float* r0 = ob + (size_t)(sg[0]*4 + 0)*DM;
        float* r1 = ob + (size_t)(sg[1]*4 + 1)*DM;
        float* r2 = ob + (size_t)(sg[2]*4 + 2)*DM;
        float* r3 = ob + (size_t)(sg[3]*4 + 3)*DM;
        #pragma unroll
        for (int j = 0; j < 4; j++) atomicAdd(r0 + j, o0[j]);
        #pragma unroll
        for (int j = 0; j < 4; j++) atomicAdd(r1 + j, o1[j]);
        #pragma unroll
        for (int j = 0; j < 4; j++) atomicAdd(r2 + j, o2[j]);
        #pragma unroll
        for (int j = 0; j < 4; j++) atomicAdd(r3 + j, o3[j]);
    }
}

extern "C" void kernel_launch(void* const* d_in, const int* in_sizes, int n_in,
                              void* d_out, int out_size)
{
    const float* x    = (const float*)d_in[0];
    const float* ctrl = (const float*)d_in[1];
    const float* f1   = (const float*)d_in[2];
    const float* bias = (const float*)d_in[3];
    const float* f2   = (const float*)d_in[4];
    float* out = (float*)d_out;

    cudaFuncSetAttribute(k_logits, cudaFuncAttributeMaxDynamicSharedMemorySize, SMEM1);

    k_logits<<<128, 1024, SMEM1>>>(x, ctrl, out);
    k_sel<<<BATCH*TT*NEXP, 256>>>();
    k_expert<<<BATCH*NEXP*4, 256>>>(x, f1, bias, f2, out);
}

// round 16
// speedup vs baseline: 1.0090x; 1.0090x over previous
#include <cuda_runtime.h>
#include <cstdint>
#include <math.h>

#define DM   1024
#define NEXP 32
#define FE   128
#define TT   4
#define BATCH 4
#define SEQ  4096
#define NTOK (BATCH*SEQ)   // 16384
#define NGRP (SEQ/TT)      // 1024

typedef unsigned long long ull;

// scratch (device globals; no allocation)
__device__ float g_logitsT[BATCH*TT*NEXP*NGRP];   // 2MB [(b*4+t)*32+e][g]
__device__ int   g_selg[BATCH*TT*NEXP];
__device__ float g_selp[BATCH*TT*NEXP];

__device__ __forceinline__ ull pack2(float a, float b) {
    ull r; asm("mov.b64 %0,{%1,%2};" : "=l"(r) : "f"(a), "f"(b)); return r;
}
__device__ __forceinline__ void unpack2(ull v, float& a, float& b) {
    asm("mov.b64 {%0,%1},%2;" : "=f"(a), "=f"(b) : "l"(v));
}
__device__ __forceinline__ void ffma2(ull& d, ull a, ull b) {
    asm("fma.rn.f32x2 %0,%1,%2,%0;" : "+l"(d) : "l"(a), "l"(b));
}

// ---------------------------------------------------------------------------
// K1: zero output + logits GEMM (R13 pair-pipeline, proven 46.4us).
// 128 blocks x 512 threads; warp = (eq, ks); thread tile 4 tok x 8 exp;
// x staged transposed [k][tok] pad-129; chunk-pair pipeline, 16 barriers.
// ---------------------------------------------------------------------------
#define XKROW 129
#define XKBUF (32*XKROW)
#define SMEM1 (131072 + 4*XKBUF*4)              // 197120

__device__ __forceinline__ void compute_chunk(
    const float* __restrict__ xb, const ull* __restrict__ ctrl_s,
    int c, int ks, int eq, int tg, ull acc[4][4])
{
    #pragma unroll
    for (int u = 0; u < 8; u++) {
        const ulonglong2* cb = reinterpret_cast<const ulonglong2*>(
            ctrl_s + (size_t)(c*32 + ks*8 + u)*16 + eq*4);
        ulonglong2 q0 = cb[0], q1 = cb[1];
        ull cu0 = q0.x, cu1 = q0.y, cu2 = q1.x, cu3 = q1.y;
        const float* xrow = xb + (ks*8 + u)*XKROW + tg;
        #pragma unroll
        for (int i = 0; i < 4; i++) {
            float xf = xrow[32*i];
            ull x2 = pack2(xf, xf);
            ffma2(acc[i][0], x2, cu0);
            ffma2(acc[i][1], x2, cu1);
            ffma2(acc[i][2], x2, cu2);
            ffma2(acc[i][3], x2, cu3);
        }
    }
}

__global__ void __launch_bounds__(512, 1)
k_logits(const float* __restrict__ x, const float* __restrict__ ctrl,
         float* __restrict__ out)
{
    extern __shared__ char smraw[];
    ull*   ctrl_s = reinterpret_cast<ull*>(smraw);              // [1024k][16 ull]
    float* xk     = reinterpret_cast<float*>(smraw + 131072);   // 4 x [32][129]

    const int tid = threadIdx.x;
    const int tg  = tid & 31;
    const int w   = tid >> 5;
    const int eq  = w >> 2;
    const int ks  = w & 3;
    const int tb  = blockIdx.x;
    const float* xblk = x + (size_t)tb * 128 * DM;

    // fire-and-forget zero of this block's output slab
    {
        float4 z = make_float4(0.f, 0.f, 0.f, 0.f);
        float4* op = reinterpret_cast<float4*>(out) + (size_t)tb * 32768;
        #pragma unroll
        for (int i = 0; i < 64; i++) op[tid + i*512] = z;
    }

    const int s_tok0 = tid >> 3;
    const int s_kq   = tid & 7;
    const float* sbase  = xblk + (size_t)s_tok0*DM + s_kq*4;
    const float* sbase2 = sbase + (size_t)64*DM;

    float4 ra0 = *reinterpret_cast<const float4*>(sbase);
    float4 ra1 = *reinterpret_cast<const float4*>(sbase2);
    float4 rb0 = *reinterpret_cast<const float4*>(sbase  + 32);
    float4 rb1 = *reinterpret_cast<const float4*>(sbase2 + 32);

    {
        const float4* cg4 = reinterpret_cast<const float4*>(ctrl);
        float4* cs4 = reinterpret_cast<float4*>(ctrl_s);
        #pragma unroll
        for (int i = 0; i < 16; i++) cs4[tid + i*512] = cg4[tid + i*512];
    }
    {
        const float* pa0 = reinterpret_cast<const float*>(&ra0);
        const float* pa1 = reinterpret_cast<const float*>(&ra1);
        const float* pb0 = reinterpret_cast<const float*>(&rb0);
        const float* pb1 = reinterpret_cast<const float*>(&rb1);
        float* b0 = xk;
        float* b1 = xk + XKBUF;
        #pragma unroll
        for (int j = 0; j < 4; j++) {
            b0[(s_kq*4 + j)*XKROW + s_tok0]      = pa0[j];
            b0[(s_kq*4 + j)*XKROW + s_tok0 + 64] = pa1[j];
            b1[(s_kq*4 + j)*XKROW + s_tok0]      = pb0[j];
            b1[(s_kq*4 + j)*XKROW + s_tok0 + 64] = pb1[j];
        }
    }
    __syncthreads();

    ull acc[4][4];
    #pragma unroll
    for (int i = 0; i < 4; i++)
        #pragma unroll
        for (int p = 0; p < 4; p++) acc[i][p] = 0ull;

    #pragma unroll 2
    for (int p = 0; p < 16; p++) {
        const int s = p & 1;
        if (p < 15) {
            ra0 = *reinterpret_cast<const float4*>(sbase  + (2*p+2)*32);
            ra1 = *reinterpret_cast<const float4*>(sbase2 + (2*p+2)*32);
            rb0 = *reinterpret_cast<const float4*>(sbase  + (2*p+3)*32);
            rb1 = *reinterpret_cast<const float4*>(sbase2 + (2*p+3)*32);
        }
        compute_chunk(xk + (2*s)*XKBUF,     ctrl_s, 2*p,     ks, eq, tg, acc);
        compute_chunk(xk + (2*s + 1)*XKBUF, ctrl_s, 2*p + 1, ks, eq, tg, acc);
        if (p < 15) {
            float* b0 = xk + (2*(1 - s))*XKBUF;
            float* b1 = xk + (2*(1 - s) + 1)*XKBUF;
            const float* pa0 = reinterpret_cast<const float*>(&ra0);
            const float* pa1 = reinterpret_cast<const float*>(&ra1);
            const float* pb0 = reinterpret_cast<const float*>(&rb0);
            const float* pb1 = reinterpret_cast<const float*>(&rb1);
            #pragma unroll
            for (int j = 0; j < 4; j++) {
                b0[(s_kq*4 + j)*XKROW + s_tok0]      = pa0[j];
                b0[(s_kq*4 + j)*XKROW + s_tok0 + 64] = pa1[j];
                b1[(s_kq*4 + j)*XKROW + s_tok0]      = pb0[j];
                b1[(s_kq*4 + j)*XKROW + s_tok0 + 64] = pb1[j];
            }
        }
        __syncthreads();
    }

    ull* red = ctrl_s;
    #pragma unroll
    for (int i = 0; i < 4; i++)
        #pragma unroll
        for (int p = 0; p < 4; p++)
            red[(((size_t)(eq*4 + ks)*128) + (tg + 32*i))*4 + p] = acc[i][p];
    __syncthreads();

    #pragma unroll
    for (int j = 0; j < 4; j++) {
        int s = tid*4 + j;
        int tok = s >> 4, pr = s & 15;
        int peq = pr >> 2, pp = pr & 3;
        float lo = 0.f, hi = 0.f;
        #pragma unroll
        for (int k2 = 0; k2 < 4; k2++) {
            float a, b;
            unpack2(red[(((size_t)(peq*4 + k2)*128) + tok)*4 + pp], a, b);
            lo += a; hi += b;
        }
        int gt = tb*128 + tok;
        int b  = gt >> 12;
        int sg = gt & 4095;
        int g  = sg >> 2, t = sg & 3;
        float tbk = (float)t * (1e-6f / 3.0f);   // linspace(0,1e-6,4)[t]
        int row = (b*4 + t)*32 + 2*pr;
        g_logitsT[(size_t)row*1024 + g]     = lo + tbk;
        g_logitsT[(size_t)(row+1)*1024 + g] = hi + tbk;
    }
}

// ---------------------------------------------------------------------------
// K_sel: one block per (b,t,e) row: argmax + softmax denominator over 1024 g.
// ---------------------------------------------------------------------------
__global__ void __launch_bounds__(256, 8)
k_sel()
{
    __shared__ float rm[8];
    __shared__ int   rmi[8];
    __shared__ float rs[8];
    __shared__ float mfin;

    const int tid  = threadIdx.x;
    const int lane = tid & 31;
    const int wp   = tid >> 5;
    const float* L = g_logitsT + ((size_t)blockIdx.x << 10);

    float m = -3.4e38f; int mi = 0;
    #pragma unroll
    for (int j = 0; j < 4; j++) {
        int i = tid + j*256;
        float v = L[i];
        if (v > m) { m = v; mi = i; }
    }
    #pragma unroll
    for (int o = 16; o; o >>= 1) {
        float om = __shfl_down_sync(0xffffffffu, m, o);
        int   oi = __shfl_down_sync(0xffffffffu, mi, o);
        if (om > m || (om == m && oi < mi)) { m = om; mi = oi; }
    }
    if (lane == 0) { rm[wp] = m; rmi[wp] = mi; }
    __syncthreads();
    if (tid == 0) {
        #pragma unroll
        for (int w = 1; w < 8; w++) {
            if (rm[w] > m || (rm[w] == m && rmi[w] < mi)) { m = rm[w]; mi = rmi[w]; }
        }
        g_selg[blockIdx.x] = mi;
        mfin = m;
    }
    __syncthreads();
    m = mfin;

    float s = 0.f;
    #pragma unroll
    for (int j = 0; j < 4; j++) s += expf(L[tid + j*256] - m);
    #pragma unroll
    for (int o = 16; o; o >>= 1) s += __shfl_down_sync(0xffffffffu, s, o);
    if (lane == 0) rs[wp] = s;
    __syncthreads();
    if (tid == 0) {
        float tot = 0.f;
        #pragma unroll
        for (int w = 0; w < 8; w++) tot += rs[w];
        g_selp[blockIdx.x] = 1.0f / tot;
    }
}

// ---------------------------------------------------------------------------
// K2: b-MERGED expert path. grid 128 = (e, fs) x 512 threads.
// Block handles ALL 16 (b,t) tokens for its 32-f slice of expert e:
// f1/f2 each read exactly once chip-wide (32MB total vs 128MB before).
// up-proj -> reduce -> bias/group-mix/relu -> down-proj -> atomic scatter.
// ---------------------------------------------------------------------------
#define SMEM2 ((16*1024 + 16*16*32 + 16*32 + 16*32) * 4)   // 100352 bytes
__global__ void __launch_bounds__(512, 1)
k_expert(const float* __restrict__ x, const float* __restrict__ f1,
         const float* __restrict__ bias, const float* __restrict__ f2,
         float* __restrict__ out)
{
    extern __shared__ float sm[];
    float* xs   = sm;                    // [16][1024]
    float* part = sm + 16*1024;          // [16 w][16 r][32 f]
    float* av   = part + 16*16*32;       // [16 r][32 f]
    float* Ws   = av + 16*32;            // [16 r][32 f]
    __shared__ int   sgq[16];
    __shared__ float spq[16];

    const int tid  = threadIdx.x;
    const int lane = tid & 31;
    const int w    = tid >> 5;           // 0..15
    const int e  = blockIdx.x >> 2;
    const int fs = blockIdx.x & 3;

    if (tid < 16) {
        sgq[tid] = g_selg[tid*32 + e];   // tid = b*4 + t
        spq[tid] = g_selp[tid*32 + e];
    }
    __syncthreads();

    // stage all 16 selected token rows (16 x 1024 f = 64KB)
    #pragma unroll
    for (int i = 0; i < 8; i++) {
        int q = tid + i*512;             // 0..4095 float4 slots
        int r = q >> 8;
        int c = q & 255;
        int b = r >> 2, t = r & 3;
        reinterpret_cast<float4*>(xs + r*1024)[c] =
            reinterpret_cast<const float4*>(
                x + ((size_t)b*SEQ + sgq[r]*4 + t)*DM)[c];
    }
    __syncthreads();

    // up-projection: warp w owns d in [w*64, w*64+64); lane = f
    {
        float acc[16];
        #pragma unroll
        for (int r = 0; r < 16; r++) acc[r] = 0.f;
        const float* f1p = f1 + (size_t)(w*64)*(NEXP*FE) + e*FE + fs*32 + lane;
        #pragma unroll 4
        for (int d = 0; d < 64; d++) {
            float wv = f1p[(size_t)d * (NEXP*FE)];
            const float* xc = xs + w*64 + d;
            #pragma unroll
            for (int r = 0; r < 16; r++)
                acc[r] += xc[r*1024] * wv;
        }
        #pragma unroll
        for (int r = 0; r < 16; r++)
            part[(w*16 + r)*32 + lane] = acc[r];
    }
    __syncthreads();

    // reduce over 16 warps -> av
    {
        const int r = tid >> 5, f = tid & 31;
        float s = 0.f;
        #pragma unroll
        for (int w2 = 0; w2 < 16; w2++) s += part[(w2*16 + r)*32 + f];
        av[r*32 + f] = s;
    }
    __syncthreads();

    // bias + duplicate-group mixing + relu + p scaling -> Ws
    {
        const int r = tid >> 5, f = tid & 31;
        const int b = r >> 2;
        float sum = bias[e*FE + fs*32 + f];
        #pragma unroll
        for (int t2 = 0; t2 < 4; t2++)
            if (sgq[b*4 + t2] == sgq[r])
                sum += spq[b*4 + t2] * av[(b*4 + t2)*32 + f];
        Ws[r*32 + f] = spq[r] * fmaxf(sum, 0.f);
    }
    __syncthreads();

    // down-projection: thread owns 2 d' columns; 32 f rows; 16 tokens
    {
        float o[16][2];
        #pragma unroll
        for (int r = 0; r < 16; r++) { o[r][0] = 0.f; o[r][1] = 0.f; }
        const float* f2p = f2 + (size_t)e*FE*DM + (size_t)(fs*32)*DM + tid*2;
        #pragma unroll 4
        for (int f = 0; f < 32; f++) {
            float2 v = *reinterpret_cast<const float2*>(f2p + (size_t)f*DM);
            const float* Wf = Ws + f;
            #pragma unroll
            for (int r = 0; r < 16; r++) {
                float wv = Wf[r*32];
                o[r][0] += wv * v.x;
                o[r][1] += wv * v.y;
            }
        }
        #pragma unroll
        for (int r = 0; r < 16; r++) {
            int b = r >> 2, t = r & 3;
            float* orow = out + ((size_t)b*SEQ + sgq[r]*4 + t)*DM + tid*2;
            atomicAdd(orow,     o[r][0]);
            atomicAdd(orow + 1, o[r][1]);
        }
    }
}

extern "C" void kernel_launch(void* const* d_in, const int* in_sizes, int n_in,
                              void* d_out, int out_size)
{
    const float* x    = (const float*)d_in[0];
    const float* ctrl = (const float*)d_in[1];
    const float* f1   = (const float*)d_in[2];
    const float* bias = (const float*)d_in[3];
    const float* f2   = (const float*)d_in[4];
    float* out = (float*)d_out;

    cudaFuncSetAttribute(k_logits, cudaFuncAttributeMaxDynamicSharedMemorySize, SMEM1);
    cudaFuncSetAttribute(k_expert, cudaFuncAttributeMaxDynamicSharedMemorySize, SMEM2);

    k_logits<<<128, 512, SMEM1>>>(x, ctrl, out);
    k_sel<<<BATCH*TT*NEXP, 256>>>();
    k_expert<<<NEXP*4, 512, SMEM2>>>(x, f1, bias, f2, out);
}

// round 17
// speedup vs baseline: 1.0268x; 1.0176x over previous
#include <cuda_runtime.h>
#include <cstdint>
#include <math.h>

#define DM   1024
#define NEXP 32
#define FE   128
#define TT   4
#define BATCH 4
#define SEQ  4096
#define NTOK (BATCH*SEQ)   // 16384
#define NGRP (SEQ/TT)      // 1024

typedef unsigned long long ull;

// scratch (device globals; no allocation)
// per-(row, segment) selection stats; row = (b*4+t)*32+e, seg = token-tile
__device__ float g_smax[512*32];
__device__ int   g_sidx[512*32];
__device__ float g_ssum[512*32];

__device__ __forceinline__ ull pack2(float a, float b) {
    ull r; asm("mov.b64 %0,{%1,%2};" : "=l"(r) : "f"(a), "f"(b)); return r;
}
__device__ __forceinline__ void unpack2(ull v, float& a, float& b) {
    asm("mov.b64 {%0,%1},%2;" : "=f"(a), "=f"(b) : "l"(v));
}
__device__ __forceinline__ void ffma2(ull& d, ull a, ull b) {
    asm("fma.rn.f32x2 %0,%1,%2,%0;" : "+l"(d) : "l"(a), "l"(b));
}

// ---------------------------------------------------------------------------
// K1: zero output + logits GEMM (R13 pair-pipeline) + fused per-segment
// selection stats (max/argmax/sum-exp over this block's 32 groups).
// 128 blocks x 512 threads; warp = (eq, ks); thread tile 4 tok x 8 exp;
// x staged transposed [k][tok] pad-129; chunk-pair pipeline, 16 barriers.
// ---------------------------------------------------------------------------
#define XKROW 129
#define XKBUF (32*XKROW)
#define SMEM1 (131072 + 4*XKBUF*4)              // 197120

__device__ __forceinline__ void compute_chunk(
    const float* __restrict__ xb, const ull* __restrict__ ctrl_s,
    int c, int ks, int eq, int tg, ull acc[4][4])
{
    #pragma unroll
    for (int u = 0; u < 8; u++) {
        const ulonglong2* cb = reinterpret_cast<const ulonglong2*>(
            ctrl_s + (size_t)(c*32 + ks*8 + u)*16 + eq*4);
        ulonglong2 q0 = cb[0], q1 = cb[1];
        ull cu0 = q0.x, cu1 = q0.y, cu2 = q1.x, cu3 = q1.y;
        const float* xrow = xb + (ks*8 + u)*XKROW + tg;
        #pragma unroll
        for (int i = 0; i < 4; i++) {
            float xf = xrow[32*i];
            ull x2 = pack2(xf, xf);
            ffma2(acc[i][0], x2, cu0);
            ffma2(acc[i][1], x2, cu1);
            ffma2(acc[i][2], x2, cu2);
            ffma2(acc[i][3], x2, cu3);
        }
    }
}

__global__ void __launch_bounds__(512, 1)
k_logits(const float* __restrict__ x, const float* __restrict__ ctrl,
         float* __restrict__ out)
{
    extern __shared__ char smraw[];
    ull*   ctrl_s = reinterpret_cast<ull*>(smraw);              // [1024k][16 ull]
    float* xk     = reinterpret_cast<float*>(smraw + 131072);   // 4 x [32][129]

    const int tid = threadIdx.x;
    const int tg  = tid & 31;
    const int w   = tid >> 5;
    const int eq  = w >> 2;
    const int ks  = w & 3;
    const int tb  = blockIdx.x;
    const float* xblk = x + (size_t)tb * 128 * DM;

    // fire-and-forget zero of this block's output slab
    {
        float4 z = make_float4(0.f, 0.f, 0.f, 0.f);
        float4* op = reinterpret_cast<float4*>(out) + (size_t)tb * 32768;
        #pragma unroll
        for (int i = 0; i < 64; i++) op[tid + i*512] = z;
    }

    const int s_tok0 = tid >> 3;
    const int s_kq   = tid & 7;
    const float* sbase  = xblk + (size_t)s_tok0*DM + s_kq*4;
    const float* sbase2 = sbase + (size_t)64*DM;

    float4 ra0 = *reinterpret_cast<const float4*>(sbase);
    float4 ra1 = *reinterpret_cast<const float4*>(sbase2);
    float4 rb0 = *reinterpret_cast<const float4*>(sbase  + 32);
    float4 rb1 = *reinterpret_cast<const float4*>(sbase2 + 32);

    {
        const float4* cg4 = reinterpret_cast<const float4*>(ctrl);
        float4* cs4 = reinterpret_cast<float4*>(ctrl_s);
        #pragma unroll
        for (int i = 0; i < 16; i++) cs4[tid + i*512] = cg4[tid + i*512];
    }
    {
        const float* pa0 = reinterpret_cast<const float*>(&ra0);
        const float* pa1 = reinterpret_cast<const float*>(&ra1);
        const float* pb0 = reinterpret_cast<const float*>(&rb0);
        const float* pb1 = reinterpret_cast<const float*>(&rb1);
        float* b0 = xk;
        float* b1 = xk + XKBUF;
        #pragma unroll
        for (int j = 0; j < 4; j++) {
            b0[(s_kq*4 + j)*XKROW + s_tok0]      = pa0[j];
            b0[(s_kq*4 + j)*XKROW + s_tok0 + 64] = pa1[j];
            b1[(s_kq*4 + j)*XKROW + s_tok0]      = pb0[j];
            b1[(s_kq*4 + j)*XKROW + s_tok0 + 64] = pb1[j];
        }
    }
    __syncthreads();

    ull acc[4][4];
    #pragma unroll
    for (int i = 0; i < 4; i++)
        #pragma unroll
        for (int p = 0; p < 4; p++) acc[i][p] = 0ull;

    #pragma unroll 2
    for (int p = 0; p < 16; p++) {
        const int s = p & 1;
        if (p < 15) {
            ra0 = *reinterpret_cast<const float4*>(sbase  + (2*p+2)*32);
            ra1 = *reinterpret_cast<const float4*>(sbase2 + (2*p+2)*32);
            rb0 = *reinterpret_cast<const float4*>(sbase  + (2*p+3)*32);
            rb1 = *reinterpret_cast<const float4*>(sbase2 + (2*p+3)*32);
        }
        compute_chunk(xk + (2*s)*XKBUF,     ctrl_s, 2*p,     ks, eq, tg, acc);
        compute_chunk(xk + (2*s + 1)*XKBUF, ctrl_s, 2*p + 1, ks, eq, tg, acc);
        if (p < 15) {
            float* b0 = xk + (2*(1 - s))*XKBUF;
            float* b1 = xk + (2*(1 - s) + 1)*XKBUF;
            const float* pa0 = reinterpret_cast<const float*>(&ra0);
            const float* pa1 = reinterpret_cast<const float*>(&ra1);
            const float* pb0 = reinterpret_cast<const float*>(&rb0);
            const float* pb1 = reinterpret_cast<const float*>(&rb1);
            #pragma unroll
            for (int j = 0; j < 4; j++) {
                b0[(s_kq*4 + j)*XKROW + s_tok0]      = pa0[j];
                b0[(s_kq*4 + j)*XKROW + s_tok0 + 64] = pa1[j];
                b1[(s_kq*4 + j)*XKROW + s_tok0]      = pb0[j];
                b1[(s_kq*4 + j)*XKROW + s_tok0 + 64] = pb1[j];
            }
        }
        __syncthreads();
    }

    // reduce over 4 k-slices via smem (in ctrl_s region)
    ull* red = ctrl_s;
    #pragma unroll
    for (int i = 0; i < 4; i++)
        #pragma unroll
        for (int p = 0; p < 4; p++)
            red[(((size_t)(eq*4 + ks)*128) + (tg + 32*i))*4 + p] = acc[i][p];
    __syncthreads();

    // final logits -> Lr[row = t*32+e][g_local], reuse xk region (16KB)
    float* Lr = xk;
    #pragma unroll
    for (int j = 0; j < 4; j++) {
        int s = tid*4 + j;
        int tok = s >> 4, pr = s & 15;
        int peq = pr >> 2, pp = pr & 3;
        float lo = 0.f, hi = 0.f;
        #pragma unroll
        for (int k2 = 0; k2 < 4; k2++) {
            float a, b;
            unpack2(red[(((size_t)(peq*4 + k2)*128) + tok)*4 + pp], a, b);
            lo += a; hi += b;
        }
        int t = tok & 3, gl = tok >> 2;
        float tbk = (float)t * (1e-6f / 3.0f);   // linspace(0,1e-6,4)[t]
        Lr[(t*32 + 2*pr    )*32 + gl] = lo + tbk;
        Lr[(t*32 + 2*pr + 1)*32 + gl] = hi + tbk;
    }
    __syncthreads();

    // per-row segment stats: warp w handles 8 rows; lane = g_local
    {
        const int ln  = tid & 31;
        const int bb  = tb >> 5;
        const int seg = tb & 31;
        #pragma unroll
        for (int rr = 0; rr < 8; rr++) {
            int row = w*8 + rr;                 // t*32 + e
            float v = Lr[row*32 + ln];
            float m = v;
            int   gi = seg*32 + ln;             // global g within batch b
            #pragma unroll
            for (int o = 16; o; o >>= 1) {
                float om = __shfl_xor_sync(0xffffffffu, m, o);
                int   oi = __shfl_xor_sync(0xffffffffu, gi, o);
                if (om > m || (om == m && oi < gi)) { m = om; gi = oi; }
            }
            float sum = expf(v - m);
            #pragma unroll
            for (int o = 16; o; o >>= 1)
                sum += __shfl_xor_sync(0xffffffffu, sum, o);
            if (ln == 0) {
                int t = row >> 5, e = row & 31;
                int r = (bb*4 + t)*32 + e;
                g_smax[r*32 + seg] = m;
                g_sidx[r*32 + seg] = gi;
                g_ssum[r*32 + seg] = sum;
            }
        }
    }
}

// ---------------------------------------------------------------------------
// K2: selection-reduce + up-proj + down-proj + scatter-add, 4 f-slices.
// grid 512 = (b, e, fs) x 256 threads. Head reduces the 32 per-segment
// stats per (t) row (redundant across fs blocks, deterministic).
// ---------------------------------------------------------------------------
__global__ void __launch_bounds__(256, 4)
k_expert(const float* __restrict__ x, const float* __restrict__ f1,
         const float* __restrict__ bias, const float* __restrict__ f2,
         float* __restrict__ out)
{
    __shared__ float xs[4][DM];          // 16KB
    __shared__ float part[8][4][32];     // 4KB
    __shared__ float avs[4][32];
    __shared__ float Wsm[4][32];
    __shared__ int   sg[4];
    __shared__ float sp[4];

    const int tid  = threadIdx.x;
    const int lane = tid & 31;
    const int b  = blockIdx.x >> 7;
    const int e  = (blockIdx.x >> 2) & 31;
    const int fs = blockIdx.x & 3;

    // --- selection reduce: warp t (t<4), lane = segment ---
    if (tid < 128) {
        const int tw = tid >> 5;
        int r = (b*4 + tw)*32 + e;
        float m  = g_smax[r*32 + lane];
        int   gi = g_sidx[r*32 + lane];
        float ss = g_ssum[r*32 + lane];
        float m2 = m; int gi2 = gi;
        #pragma unroll
        for (int o = 16; o; o >>= 1) {
            float om = __shfl_xor_sync(0xffffffffu, m2, o);
            int   oi = __shfl_xor_sync(0xffffffffu, gi2, o);
            if (om > m2 || (om == m2 && oi < gi2)) { m2 = om; gi2 = oi; }
        }
        float c = ss * expf(m - m2);
        #pragma unroll
        for (int o = 16; o; o >>= 1)
            c += __shfl_xor_sync(0xffffffffu, c, o);
        if (lane == 0) { sg[tw] = gi2; sp[tw] = 1.0f / c; }
    }
    __syncthreads();

    // --- load the 4 selected token rows into smem ---
    {
        const int ts = tid >> 6;
        const int gt = tid & 63;
        const float* xr = x + ((size_t)b*SEQ + sg[ts]*4 + ts) * DM;
        float4* dst = reinterpret_cast<float4*>(xs[ts]);
        const float4* src = reinterpret_cast<const float4*>(xr);
        #pragma unroll
        for (int i = 0; i < 4; i++) dst[gt + i*64] = src[gt + i*64];
    }
    __syncthreads();

    // --- up-projection for this block's 32 f's: warp w owns 128 d ---
    {
        const int w = tid >> 5;
        float a0 = 0.f, a1 = 0.f, a2 = 0.f, a3 = 0.f;
        const float* f1p = f1 + (size_t)(w*128)*(NEXP*FE) + e*FE + fs*32 + lane;
        const float* x0 = xs[0] + w*128;
        const float* x1 = xs[1] + w*128;
        const float* x2 = xs[2] + w*128;
        const float* x3 = xs[3] + w*128;
        #pragma unroll 16
        for (int d = 0; d < 128; d++) {
            float wv = f1p[(size_t)d * (NEXP*FE)];
            a0 += x0[d]*wv; a1 += x1[d]*wv; a2 += x2[d]*wv; a3 += x3[d]*wv;
        }
        part[w][0][lane] = a0; part[w][1][lane] = a1;
        part[w][2][lane] = a2; part[w][3][lane] = a3;
    }
    __syncthreads();

    if (tid < 128) {
        const int t = tid >> 5, f = tid & 31;
        float s = 0.f;
        #pragma unroll
        for (int w = 0; w < 8; w++) s += part[w][t][f];
        avs[t][f] = s;
    }
    __syncthreads();

    if (tid < 32) {
        const int f = tid;
        float av[4] = {avs[0][f], avs[1][f], avs[2][f], avs[3][f]};
        int   gg[4] = {sg[0], sg[1], sg[2], sg[3]};
        float pp[4] = {sp[0], sp[1], sp[2], sp[3]};
        float bi = bias[e*FE + fs*32 + f];
        #pragma unroll
        for (int t = 0; t < 4; t++) {
            float sum = bi;
            #pragma unroll
            for (int t2 = 0; t2 < 4; t2++)
                if (gg[t2] == gg[t]) sum += pp[t2] * av[t2];
            Wsm[t][f] = pp[t] * fmaxf(sum, 0.f);
        }
    }
    __syncthreads();

    // --- down-projection: thread owns 4 d' columns, 32 f rows ---
    {
        float o0[4] = {0,0,0,0}, o1[4] = {0,0,0,0};
        float o2[4] = {0,0,0,0}, o3[4] = {0,0,0,0};
        const float* f2p = f2 + (size_t)e*FE*DM + (size_t)(fs*32)*DM + tid*4;
        #pragma unroll 4
        for (int f = 0; f < 32; f++) {
            float4 v = *reinterpret_cast<const float4*>(f2p + (size_t)f*DM);
            float w0 = Wsm[0][f], w1 = Wsm[1][f], w2 = Wsm[2][f], w3 = Wsm[3][f];
            o0[0] += w0*v.x; o0[1] += w0*v.y; o0[2] += w0*v.z; o0[3] += w0*v.w;
            o1[0] += w1*v.x; o1[1] += w1*v.y; o1[2] += w1*v.z; o1[3] += w1*v.w;
            o2[0] += w2*v.x; o2[1] += w2*v.y; o2[2] += w2*v.z; o2[3] += w2*v.w;
            o3[0] += w3*v.x; o3[1] += w3*v.y; o3[2] += w3*v.z; o3[3] += w3*v.w;
        }
        float* ob = out + (size_t)b*SEQ*DM + tid*4;
        float* r0 = ob + (size_t)(sg[0]*4 + 0)*DM;
        float* r1 = ob + (size_t)(sg[1]*4 + 1)*DM;
        float* r2 = ob + (size_t)(sg[2]*4 + 2)*DM;
        float* r3 = ob + (size_t)(sg[3]*4 + 3)*DM;
        #pragma unroll
        for (int j = 0; j < 4; j++) atomicAdd(r0 + j, o0[j]);
        #pragma unroll
        for (int j = 0; j < 4; j++) atomicAdd(r1 + j, o1[j]);
        #pragma unroll
        for (int j = 0; j < 4; j++) atomicAdd(r2 + j, o2[j]);
        #pragma unroll
        for (int j = 0; j < 4; j++) atomicAdd(r3 + j, o3[j]);
    }
}

extern "C" void kernel_launch(void* const* d_in, const int* in_sizes, int n_in,
                              void* d_out, int out_size)
{
    const float* x    = (const float*)d_in[0];
    const float* ctrl = (const float*)d_in[1];
    const float* f1   = (const float*)d_in[2];
    const float* bias = (const float*)d_in[3];
    const float* f2   = (const float*)d_in[4];
    float* out = (float*)d_out;

    cudaFuncSetAttribute(k_logits, cudaFuncAttributeMaxDynamicSharedMemorySize, SMEM1);

    k_logits<<<128, 512, SMEM1>>>(x, ctrl, out);
    k_expert<<<BATCH*NEXP*4, 256>>>(x, f1, bias, f2, out);
}